// round 1
// baseline (speedup 1.0000x reference)
#include <cuda_runtime.h>
#include <cuda_bf16.h>
#include <math.h>

// Problem constants
#define BATCH 4
#define SEQ   4096
#define EMB   1024
#define HEAD  64
#define ROWS  (BATCH * SEQ)          // 16384
#define SCALE 0.03125f               // 1/sqrt(1024)

// Scratch for q, k, v: [B*T, 64] each
__device__ float g_q[(size_t)ROWS * HEAD];
__device__ float g_k[(size_t)ROWS * HEAD];
__device__ float g_v[(size_t)ROWS * HEAD];

// ---------------------------------------------------------------------------
// Kernel 1: qkv projection. grid = (ROWS/64, 3), block = 256.
// out[r][c] = sum_k x[r][k] * W[k][c]
// Register 4x4 micro-tiles; x staged transposed in smem so the inner loop is
// two LDS.128 + 16 FFMA per k.
// ---------------------------------------------------------------------------
__global__ __launch_bounds__(256) void qkv_kernel(
    const float* __restrict__ x,
    const float* __restrict__ Wq,
    const float* __restrict__ Wk,
    const float* __restrict__ Wv)
{
    const int rowTile = blockIdx.x;           // 0..255
    const int m       = blockIdx.y;           // 0..2
    const float* __restrict__ W = (m == 0) ? Wq : (m == 1) ? Wk : Wv;
    float* __restrict__ out     = (m == 0) ? g_q : (m == 1) ? g_k : g_v;

    __shared__ float Xt[32][68];   // [k][r]  (transposed x chunk)
    __shared__ float Ws[32][64];   // [k][c]

    const int tid = threadIdx.x;
    const int tx  = tid & 15;
    const int ty  = tid >> 4;
    const int r0  = ty * 4;
    const int c0  = tx * 4;
    const int rowBase = rowTile * 64;

    float acc[4][4];
#pragma unroll
    for (int i = 0; i < 4; i++)
#pragma unroll
        for (int j = 0; j < 4; j++) acc[i][j] = 0.0f;

    for (int kc = 0; kc < EMB; kc += 32) {
        // Load x chunk: 64 rows x 32 cols = 512 float4 (transposed into Xt)
        for (int s = tid; s < 512; s += 256) {
            int r  = s >> 3;          // 8 float4 per row
            int k4 = s & 7;
            float4 vx = *(const float4*)&x[(size_t)(rowBase + r) * EMB + kc + k4 * 4];
            Xt[k4 * 4 + 0][r] = vx.x;
            Xt[k4 * 4 + 1][r] = vx.y;
            Xt[k4 * 4 + 2][r] = vx.z;
            Xt[k4 * 4 + 3][r] = vx.w;
        }
        // Load W chunk: 32 rows x 64 cols = 512 float4
        for (int s = tid; s < 512; s += 256) {
            int k  = s >> 4;
            int c4 = s & 15;
            *(float4*)&Ws[k][c4 * 4] =
                *(const float4*)&W[(size_t)(kc + k) * HEAD + c4 * 4];
        }
        __syncthreads();

#pragma unroll 8
        for (int k = 0; k < 32; k++) {
            float4 a = *(const float4*)&Xt[k][r0];
            float4 b = *(const float4*)&Ws[k][c0];
            acc[0][0] += a.x * b.x; acc[0][1] += a.x * b.y; acc[0][2] += a.x * b.z; acc[0][3] += a.x * b.w;
            acc[1][0] += a.y * b.x; acc[1][1] += a.y * b.y; acc[1][2] += a.y * b.z; acc[1][3] += a.y * b.w;
            acc[2][0] += a.z * b.x; acc[2][1] += a.z * b.y; acc[2][2] += a.z * b.z; acc[2][3] += a.z * b.w;
            acc[3][0] += a.w * b.x; acc[3][1] += a.w * b.y; acc[3][2] += a.w * b.z; acc[3][3] += a.w * b.w;
        }
        __syncthreads();
    }

#pragma unroll
    for (int i = 0; i < 4; i++) {
        float4 vo = make_float4(acc[i][0], acc[i][1], acc[i][2], acc[i][3]);
        *(float4*)&out[(size_t)(rowBase + r0 + i) * HEAD + c0] = vo;
    }
}

// ---------------------------------------------------------------------------
// Kernel 2: causal flash attention. grid = (SEQ/64, BATCH), block = 256.
// Each block owns a 64-query tile, iterates key tiles 0..qt with online
// softmax. All GEMMs are 4x4 register micro-tiles with float4 smem operands.
// Dynamic smem: Qt[64][68] + Kt[64][68] + Pt[64][68] + Vs[64][64]
// ---------------------------------------------------------------------------
__global__ __launch_bounds__(256) void attn_kernel(float* __restrict__ out)
{
    extern __shared__ float smem[];
    float* Qt = smem;                   // [d][r]  stride 68
    float* Kt = Qt + 64 * 68;           // [d][c]  stride 68
    float* Pt = Kt + 64 * 68;           // [c][r]  stride 68
    float* Vs = Pt + 64 * 68;           // [c][h]  stride 64

    const int b  = blockIdx.y;
    const int qt = (int)gridDim.x - 1 - (int)blockIdx.x;  // big tiles first
    const int qbase = qt * 64;

    const float* __restrict__ q = g_q + (size_t)b * SEQ * HEAD;
    const float* __restrict__ k = g_k + (size_t)b * SEQ * HEAD;
    const float* __restrict__ v = g_v + (size_t)b * SEQ * HEAD;

    const int tid = threadIdx.x;
    const int tx  = tid & 15;
    const int ty  = tid >> 4;
    const int r0  = ty * 4;
    const int c0  = tx * 4;

    // Load Q tile transposed (once)
    for (int s = tid; s < 1024; s += 256) {     // 64 rows x 16 float4
        int r  = s >> 4;
        int d4 = s & 15;
        float4 vq = *(const float4*)&q[(size_t)(qbase + r) * HEAD + d4 * 4];
        Qt[(d4 * 4 + 0) * 68 + r] = vq.x;
        Qt[(d4 * 4 + 1) * 68 + r] = vq.y;
        Qt[(d4 * 4 + 2) * 68 + r] = vq.z;
        Qt[(d4 * 4 + 3) * 68 + r] = vq.w;
    }

    float o[4][4];
    float mrow[4], lrow[4];
#pragma unroll
    for (int i = 0; i < 4; i++) {
        mrow[i] = -1e30f;
        lrow[i] = 0.0f;
#pragma unroll
        for (int j = 0; j < 4; j++) o[i][j] = 0.0f;
    }

    for (int jt = 0; jt <= qt; jt++) {
        const int kbase = jt * 64;
        __syncthreads();   // prev-iter readers of Kt/Vs/Pt done; Qt load done (jt=0)

        // Load K tile transposed + V tile direct: 64 x 16 float4 each
        for (int s = tid; s < 1024; s += 256) {
            int c  = s >> 4;
            int d4 = s & 15;
            float4 vk = *(const float4*)&k[(size_t)(kbase + c) * HEAD + d4 * 4];
            Kt[(d4 * 4 + 0) * 68 + c] = vk.x;
            Kt[(d4 * 4 + 1) * 68 + c] = vk.y;
            Kt[(d4 * 4 + 2) * 68 + c] = vk.z;
            Kt[(d4 * 4 + 3) * 68 + c] = vk.w;
            *(float4*)&Vs[c * 64 + d4 * 4] =
                *(const float4*)&v[(size_t)(kbase + c) * HEAD + d4 * 4];
        }
        __syncthreads();

        // S = Q K^T * scale  (4x4 per thread)
        float s4[4][4];
#pragma unroll
        for (int i = 0; i < 4; i++)
#pragma unroll
            for (int j = 0; j < 4; j++) s4[i][j] = 0.0f;

#pragma unroll 8
        for (int d = 0; d < 64; d++) {
            float4 a = *(const float4*)&Qt[d * 68 + r0];
            float4 bb = *(const float4*)&Kt[d * 68 + c0];
            s4[0][0] += a.x * bb.x; s4[0][1] += a.x * bb.y; s4[0][2] += a.x * bb.z; s4[0][3] += a.x * bb.w;
            s4[1][0] += a.y * bb.x; s4[1][1] += a.y * bb.y; s4[1][2] += a.y * bb.z; s4[1][3] += a.y * bb.w;
            s4[2][0] += a.z * bb.x; s4[2][1] += a.z * bb.y; s4[2][2] += a.z * bb.z; s4[2][3] += a.z * bb.w;
            s4[3][0] += a.w * bb.x; s4[3][1] += a.w * bb.y; s4[3][2] += a.w * bb.z; s4[3][3] += a.w * bb.w;
        }

        const bool diag = (jt == qt);
#pragma unroll
        for (int i = 0; i < 4; i++) {
#pragma unroll
            for (int j = 0; j < 4; j++) {
                float sv = s4[i][j] * SCALE;
                if (diag && (c0 + j > r0 + i)) sv = -1e30f;
                s4[i][j] = sv;
            }
        }

        // Online softmax: per-row reduction across the 16 lanes sharing ty
#pragma unroll
        for (int i = 0; i < 4; i++) {
            float tm = fmaxf(fmaxf(s4[i][0], s4[i][1]), fmaxf(s4[i][2], s4[i][3]));
            tm = fmaxf(tm, __shfl_xor_sync(0xffffffffu, tm, 1));
            tm = fmaxf(tm, __shfl_xor_sync(0xffffffffu, tm, 2));
            tm = fmaxf(tm, __shfl_xor_sync(0xffffffffu, tm, 4));
            tm = fmaxf(tm, __shfl_xor_sync(0xffffffffu, tm, 8));
            float nm    = fmaxf(mrow[i], tm);
            float alpha = __expf(mrow[i] - nm);
            float ts = 0.0f;
#pragma unroll
            for (int j = 0; j < 4; j++) {
                float p = __expf(s4[i][j] - nm);
                Pt[(c0 + j) * 68 + (r0 + i)] = p;
                ts += p;
            }
            ts += __shfl_xor_sync(0xffffffffu, ts, 1);
            ts += __shfl_xor_sync(0xffffffffu, ts, 2);
            ts += __shfl_xor_sync(0xffffffffu, ts, 4);
            ts += __shfl_xor_sync(0xffffffffu, ts, 8);
            lrow[i] = lrow[i] * alpha + ts;
            mrow[i] = nm;
#pragma unroll
            for (int j = 0; j < 4; j++) o[i][j] *= alpha;
        }
        __syncthreads();   // Pt fully written

        // O += P V  (4x4 per thread; c0 here indexes head dim)
#pragma unroll 8
        for (int c = 0; c < 64; c++) {
            float4 a = *(const float4*)&Pt[c * 68 + r0];
            float4 bb = *(const float4*)&Vs[c * 64 + c0];
            o[0][0] += a.x * bb.x; o[0][1] += a.x * bb.y; o[0][2] += a.x * bb.z; o[0][3] += a.x * bb.w;
            o[1][0] += a.y * bb.x; o[1][1] += a.y * bb.y; o[1][2] += a.y * bb.z; o[1][3] += a.y * bb.w;
            o[2][0] += a.z * bb.x; o[2][1] += a.z * bb.y; o[2][2] += a.z * bb.z; o[2][3] += a.z * bb.w;
            o[3][0] += a.w * bb.x; o[3][1] += a.w * bb.y; o[3][2] += a.w * bb.z; o[3][3] += a.w * bb.w;
        }
    }

    // Epilogue: normalize and store
#pragma unroll
    for (int i = 0; i < 4; i++) {
        float inv = 1.0f / lrow[i];
        float4 vo = make_float4(o[i][0] * inv, o[i][1] * inv, o[i][2] * inv, o[i][3] * inv);
        size_t row = (size_t)b * SEQ + qbase + r0 + i;
        *(float4*)&out[row * HEAD + c0] = vo;
    }
}

// ---------------------------------------------------------------------------
extern "C" void kernel_launch(void* const* d_in, const int* in_sizes, int n_in,
                              void* d_out, int out_size)
{
    const float* x  = (const float*)d_in[0];
    const float* Wq = (const float*)d_in[1];
    const float* Wk = (const float*)d_in[2];
    const float* Wv = (const float*)d_in[3];
    float* out = (float*)d_out;

    // QKV projection
    {
        dim3 grid(ROWS / 64, 3);
        qkv_kernel<<<grid, 256>>>(x, Wq, Wk, Wv);
    }

    // Flash attention
    {
        const int smem_bytes = (3 * 64 * 68 + 64 * 64) * (int)sizeof(float); // 68608
        static bool attr_set = false;
        if (!attr_set) {
            cudaFuncSetAttribute(attn_kernel,
                                 cudaFuncAttributeMaxDynamicSharedMemorySize,
                                 smem_bytes);
            attr_set = true;
        }
        dim3 grid(SEQ / 64, BATCH);
        attn_kernel<<<grid, 256, smem_bytes>>>(out);
    }
}

// round 3
// speedup vs baseline: 1.3009x; 1.3009x over previous
#include <cuda_runtime.h>
#include <cuda_bf16.h>
#include <math.h>

// Problem constants
#define BATCH 4
#define SEQ   4096
#define EMB   1024
#define HEAD  64
#define ROWS  (BATCH * SEQ)          // 16384
#define NQT   (SEQ / 64)             // 64 query tiles per batch
#define SCALE 0.03125f               // 1/sqrt(1024)

// Scratch for q, k, v: [B*T, 64] each
__device__ float g_q[(size_t)ROWS * HEAD];
__device__ float g_k[(size_t)ROWS * HEAD];
__device__ float g_v[(size_t)ROWS * HEAD];

// ---------------------------------------------------------------------------
// Kernel 1: fused qkv projection. grid = ROWS/64, block = 256.
// One block computes q, k, v for its 64 rows: x is staged in smem ONCE and
// reused for all 192 output columns. Each thread owns three 4x4 micro-tiles
// (one per matrix) sharing the same a-operand -> 4 LDS.128 per 48 FFMA.
// ---------------------------------------------------------------------------
__global__ __launch_bounds__(256) void qkv_kernel(
    const float* __restrict__ x,
    const float* __restrict__ Wq,
    const float* __restrict__ Wk,
    const float* __restrict__ Wv)
{
    __shared__ float Xt[32][68];    // [k][r]  (transposed x chunk)
    __shared__ float Ws[32][192];   // [k][c]  cols 0-63 = Wq, 64-127 = Wk, 128-191 = Wv

    const int tid = threadIdx.x;
    const int tx  = tid & 15;
    const int ty  = tid >> 4;
    const int r0  = ty * 4;
    const int c0  = tx * 4;
    const int rowBase = blockIdx.x * 64;

    float aq[4][4], ak[4][4], av[4][4];
#pragma unroll
    for (int i = 0; i < 4; i++)
#pragma unroll
        for (int j = 0; j < 4; j++) { aq[i][j] = 0.f; ak[i][j] = 0.f; av[i][j] = 0.f; }

    for (int kc = 0; kc < EMB; kc += 32) {
        // x chunk: 64 rows x 32 cols, transposed into Xt
        for (int s = tid; s < 512; s += 256) {
            int r  = s >> 3;
            int k4 = s & 7;
            float4 vx = *(const float4*)&x[(size_t)(rowBase + r) * EMB + kc + k4 * 4];
            Xt[k4 * 4 + 0][r] = vx.x;
            Xt[k4 * 4 + 1][r] = vx.y;
            Xt[k4 * 4 + 2][r] = vx.z;
            Xt[k4 * 4 + 3][r] = vx.w;
        }
        // W chunks: 3 x (32 x 64)
        for (int s = tid; s < 512; s += 256) {
            int k  = s >> 4;
            int c4 = (s & 15) * 4;
            size_t off = (size_t)(kc + k) * HEAD + c4;
            *(float4*)&Ws[k][c4]       = *(const float4*)&Wq[off];
            *(float4*)&Ws[k][64 + c4]  = *(const float4*)&Wk[off];
            *(float4*)&Ws[k][128 + c4] = *(const float4*)&Wv[off];
        }
        __syncthreads();

#pragma unroll 8
        for (int k = 0; k < 32; k++) {
            float4 a  = *(const float4*)&Xt[k][r0];
            float4 bq = *(const float4*)&Ws[k][c0];
            float4 bk = *(const float4*)&Ws[k][64 + c0];
            float4 bv = *(const float4*)&Ws[k][128 + c0];
            aq[0][0] += a.x * bq.x; aq[0][1] += a.x * bq.y; aq[0][2] += a.x * bq.z; aq[0][3] += a.x * bq.w;
            aq[1][0] += a.y * bq.x; aq[1][1] += a.y * bq.y; aq[1][2] += a.y * bq.z; aq[1][3] += a.y * bq.w;
            aq[2][0] += a.z * bq.x; aq[2][1] += a.z * bq.y; aq[2][2] += a.z * bq.z; aq[2][3] += a.z * bq.w;
            aq[3][0] += a.w * bq.x; aq[3][1] += a.w * bq.y; aq[3][2] += a.w * bq.z; aq[3][3] += a.w * bq.w;
            ak[0][0] += a.x * bk.x; ak[0][1] += a.x * bk.y; ak[0][2] += a.x * bk.z; ak[0][3] += a.x * bk.w;
            ak[1][0] += a.y * bk.x; ak[1][1] += a.y * bk.y; ak[1][2] += a.y * bk.z; ak[1][3] += a.y * bk.w;
            ak[2][0] += a.z * bk.x; ak[2][1] += a.z * bk.y; ak[2][2] += a.z * bk.z; ak[2][3] += a.z * bk.w;
            ak[3][0] += a.w * bk.x; ak[3][1] += a.w * bk.y; ak[3][2] += a.w * bk.z; ak[3][3] += a.w * bk.w;
            av[0][0] += a.x * bv.x; av[0][1] += a.x * bv.y; av[0][2] += a.x * bv.z; av[0][3] += a.x * bv.w;
            av[1][0] += a.y * bv.x; av[1][1] += a.y * bv.y; av[1][2] += a.y * bv.z; av[1][3] += a.y * bv.w;
            av[2][0] += a.z * bv.x; av[2][1] += a.z * bv.y; av[2][2] += a.z * bv.z; av[2][3] += a.z * bv.w;
            av[3][0] += a.w * bv.x; av[3][1] += a.w * bv.y; av[3][2] += a.w * bv.z; av[3][3] += a.w * bv.w;
        }
        __syncthreads();
    }

#pragma unroll
    for (int i = 0; i < 4; i++) {
        size_t off = (size_t)(rowBase + r0 + i) * HEAD + c0;
        *(float4*)&g_q[off] = make_float4(aq[i][0], aq[i][1], aq[i][2], aq[i][3]);
        *(float4*)&g_k[off] = make_float4(ak[i][0], ak[i][1], ak[i][2], ak[i][3]);
        *(float4*)&g_v[off] = make_float4(av[i][0], av[i][1], av[i][2], av[i][3]);
    }
}

// ---------------------------------------------------------------------------
// Kernel 2: causal flash attention with paired q-tiles for perfect balance.
// grid = (NQT/2, BATCH) = (32, 4) = 128 blocks, block = 512 threads.
// Threads 0-255 (half 0) handle qt = 63 - p; threads 256-511 (half 1) handle
// qt = p. Total work per block = (p+1) + (64-p) = 65 key-tiles, uniform.
// The two halves are fully independent: separate smem slices and separate
// named barriers (bar.sync 1/2, 256).
// smem per half: Qt[64][68] + Kt[64][68] + Pt[64][68] + Vs[64][64] = 68608 B
// ---------------------------------------------------------------------------
#define HALF_FLOATS (3 * 64 * 68 + 64 * 64)   // 17152 floats = 68608 bytes

__global__ __launch_bounds__(512) void attn_kernel(float* __restrict__ out)
{
    extern __shared__ float smem[];
    const int half = threadIdx.x >> 8;          // 0 or 1
    const int tid  = threadIdx.x & 255;
    const int barid = half + 1;

    float* Qt = smem + half * HALF_FLOATS;      // [d][r]  stride 68
    float* Kt = Qt + 64 * 68;                   // [d][c]  stride 68
    float* Pt = Kt + 64 * 68;                   // [c][r]  stride 68
    float* Vs = Pt + 64 * 68;                   // [c][h]  stride 64

    const int b  = blockIdx.y;
    const int p  = blockIdx.x;                  // 0..31
    const int qt = half ? p : (NQT - 1 - p);    // long tile to half 0
    const int qbase = qt * 64;

    const float* __restrict__ q = g_q + (size_t)b * SEQ * HEAD;
    const float* __restrict__ k = g_k + (size_t)b * SEQ * HEAD;
    const float* __restrict__ v = g_v + (size_t)b * SEQ * HEAD;

    const int tx = tid & 15;
    const int ty = tid >> 4;
    const int r0 = ty * 4;
    const int c0 = tx * 4;

#define BSYNC() asm volatile("bar.sync %0, 256;" :: "r"(barid) : "memory")

    // Load Q tile transposed (once)
    for (int s = tid; s < 1024; s += 256) {     // 64 rows x 16 float4
        int r  = s >> 4;
        int d4 = s & 15;
        float4 vq = *(const float4*)&q[(size_t)(qbase + r) * HEAD + d4 * 4];
        Qt[(d4 * 4 + 0) * 68 + r] = vq.x;
        Qt[(d4 * 4 + 1) * 68 + r] = vq.y;
        Qt[(d4 * 4 + 2) * 68 + r] = vq.z;
        Qt[(d4 * 4 + 3) * 68 + r] = vq.w;
    }

    float o[4][4];
    float mrow[4], lrow[4];
#pragma unroll
    for (int i = 0; i < 4; i++) {
        mrow[i] = -1e30f;
        lrow[i] = 0.0f;
#pragma unroll
        for (int j = 0; j < 4; j++) o[i][j] = 0.0f;
    }

    for (int jt = 0; jt <= qt; jt++) {
        const int kbase = jt * 64;
        BSYNC();   // prev-iter readers of Kt/Vs/Pt done; Qt load done (jt=0)

        // Load K tile transposed + V tile direct
        for (int s = tid; s < 1024; s += 256) {
            int c  = s >> 4;
            int d4 = s & 15;
            float4 vk = *(const float4*)&k[(size_t)(kbase + c) * HEAD + d4 * 4];
            Kt[(d4 * 4 + 0) * 68 + c] = vk.x;
            Kt[(d4 * 4 + 1) * 68 + c] = vk.y;
            Kt[(d4 * 4 + 2) * 68 + c] = vk.z;
            Kt[(d4 * 4 + 3) * 68 + c] = vk.w;
            *(float4*)&Vs[c * 64 + d4 * 4] =
                *(const float4*)&v[(size_t)(kbase + c) * HEAD + d4 * 4];
        }
        BSYNC();

        // S = Q K^T * scale
        float s4[4][4];
#pragma unroll
        for (int i = 0; i < 4; i++)
#pragma unroll
            for (int j = 0; j < 4; j++) s4[i][j] = 0.0f;

#pragma unroll 8
        for (int d = 0; d < 64; d++) {
            float4 a  = *(const float4*)&Qt[d * 68 + r0];
            float4 bb = *(const float4*)&Kt[d * 68 + c0];
            s4[0][0] += a.x * bb.x; s4[0][1] += a.x * bb.y; s4[0][2] += a.x * bb.z; s4[0][3] += a.x * bb.w;
            s4[1][0] += a.y * bb.x; s4[1][1] += a.y * bb.y; s4[1][2] += a.y * bb.z; s4[1][3] += a.y * bb.w;
            s4[2][0] += a.z * bb.x; s4[2][1] += a.z * bb.y; s4[2][2] += a.z * bb.z; s4[2][3] += a.z * bb.w;
            s4[3][0] += a.w * bb.x; s4[3][1] += a.w * bb.y; s4[3][2] += a.w * bb.z; s4[3][3] += a.w * bb.w;
        }

        const bool diag = (jt == qt);
#pragma unroll
        for (int i = 0; i < 4; i++) {
#pragma unroll
            for (int j = 0; j < 4; j++) {
                float sv = s4[i][j] * SCALE;
                if (diag && (c0 + j > r0 + i)) sv = -1e30f;
                s4[i][j] = sv;
            }
        }

        // Online softmax: per-row reduction across the 16 lanes sharing ty
#pragma unroll
        for (int i = 0; i < 4; i++) {
            float tm = fmaxf(fmaxf(s4[i][0], s4[i][1]), fmaxf(s4[i][2], s4[i][3]));
            tm = fmaxf(tm, __shfl_xor_sync(0xffffffffu, tm, 1));
            tm = fmaxf(tm, __shfl_xor_sync(0xffffffffu, tm, 2));
            tm = fmaxf(tm, __shfl_xor_sync(0xffffffffu, tm, 4));
            tm = fmaxf(tm, __shfl_xor_sync(0xffffffffu, tm, 8));
            float nm    = fmaxf(mrow[i], tm);
            float alpha = __expf(mrow[i] - nm);
            float ts = 0.0f;
#pragma unroll
            for (int j = 0; j < 4; j++) {
                float pv = __expf(s4[i][j] - nm);
                Pt[(c0 + j) * 68 + (r0 + i)] = pv;
                ts += pv;
            }
            ts += __shfl_xor_sync(0xffffffffu, ts, 1);
            ts += __shfl_xor_sync(0xffffffffu, ts, 2);
            ts += __shfl_xor_sync(0xffffffffu, ts, 4);
            ts += __shfl_xor_sync(0xffffffffu, ts, 8);
            lrow[i] = lrow[i] * alpha + ts;
            mrow[i] = nm;
#pragma unroll
            for (int j = 0; j < 4; j++) o[i][j] *= alpha;
        }
        BSYNC();   // Pt fully written

        // O += P V
#pragma unroll 8
        for (int c = 0; c < 64; c++) {
            float4 a  = *(const float4*)&Pt[c * 68 + r0];
            float4 bb = *(const float4*)&Vs[c * 64 + c0];
            o[0][0] += a.x * bb.x; o[0][1] += a.x * bb.y; o[0][2] += a.x * bb.z; o[0][3] += a.x * bb.w;
            o[1][0] += a.y * bb.x; o[1][1] += a.y * bb.y; o[1][2] += a.y * bb.z; o[1][3] += a.y * bb.w;
            o[2][0] += a.z * bb.x; o[2][1] += a.z * bb.y; o[2][2] += a.z * bb.z; o[2][3] += a.z * bb.w;
            o[3][0] += a.w * bb.x; o[3][1] += a.w * bb.y; o[3][2] += a.w * bb.z; o[3][3] += a.w * bb.w;
        }
    }

    // Epilogue: normalize and store
#pragma unroll
    for (int i = 0; i < 4; i++) {
        float inv = 1.0f / lrow[i];
        float4 vo = make_float4(o[i][0] * inv, o[i][1] * inv, o[i][2] * inv, o[i][3] * inv);
        size_t row = (size_t)b * SEQ + qbase + r0 + i;
        *(float4*)&out[row * HEAD + c0] = vo;
    }
#undef BSYNC
}

// ---------------------------------------------------------------------------
extern "C" void kernel_launch(void* const* d_in, const int* in_sizes, int n_in,
                              void* d_out, int out_size)
{
    const float* x  = (const float*)d_in[0];
    const float* Wq = (const float*)d_in[1];
    const float* Wk = (const float*)d_in[2];
    const float* Wv = (const float*)d_in[3];
    float* out = (float*)d_out;

    // Fused QKV projection
    qkv_kernel<<<ROWS / 64, 256>>>(x, Wq, Wk, Wv);

    // Paired-tile flash attention
    {
        const int smem_bytes = 2 * HALF_FLOATS * (int)sizeof(float); // 137216
        static bool attr_set = false;
        if (!attr_set) {
            cudaFuncSetAttribute(attn_kernel,
                                 cudaFuncAttributeMaxDynamicSharedMemorySize,
                                 smem_bytes);
            attr_set = true;
        }
        dim3 grid(NQT / 2, BATCH);
        attn_kernel<<<grid, 512, smem_bytes>>>(out);
    }
}